// round 2
// baseline (speedup 1.0000x reference)
#include <cuda_runtime.h>

#define NBLK 24
#define BATCH 256
#define CH 32
#define SKP 32
#define TQ 256
#define TQO 257
#define HID 128

#define COMPUTE_CTAS 64
#define COPY_CTAS 1024
#define TPB 128

// Shared weight staging uses 36-float row pitch so that lane-indexed rows map
// to distinct banks per LDS.128 quarter-warp phase (lane*36 mod 32 = 4*lane).
__global__ void __launch_bounds__(TPB) wave_fused_kernel(
    const float* __restrict__ queues,   // (24,256,32,256)
    const float* __restrict__ x,        // (256,1,1)
    const float* __restrict__ num,      // (256,8,1)
    const int*   __restrict__ cat,      // (256,1,1)
    const float* __restrict__ emb,      // (1000,16)
    const float* __restrict__ W_in,     // (32,25)
    const float* __restrict__ b_in,     // (32)
    const float* __restrict__ W_conv,   // (24,64,32,2)
    const float* __restrict__ b_conv,   // (24,64)
    const float* __restrict__ W_res,    // (24,32,32)
    const float* __restrict__ b_res,    // (24,32)
    const float* __restrict__ W_skip,   // (24,32,32)
    const float* __restrict__ b_skip,   // (24,32)
    const float* __restrict__ W_o1,     // (128,768)
    const float* __restrict__ b_o1,     // (128)
    const float* __restrict__ W_o2,     // (1,128)
    const float* __restrict__ b_o2,     // (1)
    float* __restrict__ out)            // [256 out][24*256*32*257 new_queues]
{
    __shared__ __align__(16) float s_wc0[64 * 36];   // W_conv[..,0]  [o][c]
    __shared__ __align__(16) float s_wc1[64 * 36];   // W_conv[..,1]  [o][c]
    __shared__ __align__(16) float s_wrs[32 * 36];   // W_res  [o][s]
    __shared__ __align__(16) float s_wsk[32 * 36];   // W_skip [o][s]
    __shared__ __align__(16) float s_wo1[128 * 36];  // W_o1 chunk [h][s]
    __shared__ __align__(16) float s_tap[4][32];
    __shared__ __align__(16) float s_cur[4][32];
    __shared__ __align__(16) float s_g[4][32];

    const int tid = threadIdx.x;
    float* __restrict__ nq = out + BATCH;  // new_queues region

    if (blockIdx.x >= COMPUTE_CTAS) {
        // ---------------- COPY ROLE: queues -> new_queues[:, :, :, 0:256] ----
        const int cid = blockIdx.x - COMPUTE_CTAS;
        const float4* __restrict__ in4 = (const float4*)queues;
        const int NJ = NBLK * BATCH * CH * (TQ / 16);  // 3,145,728 chunks of 64B
        const int stride = COPY_CTAS * TPB;
        for (int j = cid * TPB + tid; j < NJ; j += stride) {
            const int row = j >> 4;          // which (i,b,c) row
            const int t4  = (j & 15) << 2;   // float4 index within row (0..60)
            const float4* src = in4 + row * 64 + t4;
            float4 v0 = src[0];
            float4 v1 = src[1];
            float4 v2 = src[2];
            float4 v3 = src[3];
            float* p = nq + (size_t)row * TQO + t4 * 4;
            p[0]  = v0.x; p[1]  = v0.y; p[2]  = v0.z; p[3]  = v0.w;
            p[4]  = v1.x; p[5]  = v1.y; p[6]  = v1.z; p[7]  = v1.w;
            p[8]  = v2.x; p[9]  = v2.y; p[10] = v2.z; p[11] = v2.w;
            p[12] = v3.x; p[13] = v3.y; p[14] = v3.z; p[15] = v3.w;
        }
        return;
    }

    // ---------------- COMPUTE ROLE: recurrent chain, 1 warp = 1 batch -------
    const int w    = tid >> 5;
    const int lane = tid & 31;
    const int b    = blockIdx.x * 4 + w;

    // --- input projection: inp = [x(1), num(8), emb(16)], cur = W_in @ inp ---
    if (lane < 25) {
        float v;
        if (lane == 0)      v = x[b];
        else if (lane < 9)  v = num[b * 8 + (lane - 1)];
        else                v = emb[cat[b] * 16 + (lane - 9)];
        s_g[w][lane] = v;
    }
    __syncwarp();
    float cur = b_in[lane];
#pragma unroll
    for (int k = 0; k < 25; k++)
        cur += W_in[lane * 25 + k] * s_g[w][k];
    __syncwarp();

    float acc0 = 0.f, acc1 = 0.f, acc2 = 0.f, acc3 = 0.f;  // W_o1 accumulators

    for (int i = 0; i < NBLK; i++) {
        __syncthreads();  // previous iteration done reading weight buffers

        // --- cooperative weight staging into padded shared -----------------
        for (int idx = tid; idx < 4096; idx += TPB) {
            const int o = idx >> 6;
            const int r = idx & 63;
            const int c = r >> 1;
            const int k = r & 1;
            const float v = W_conv[((i * 64 + o) * 32 + c) * 2 + k];
            (k ? s_wc1 : s_wc0)[o * 36 + c] = v;
        }
        for (int idx = tid; idx < 1024; idx += TPB) {
            const int o = idx >> 5;
            const int s = idx & 31;
            s_wrs[o * 36 + s] = W_res [(i * 32 + o) * 32 + s];
            s_wsk[o * 36 + s] = W_skip[(i * 32 + o) * 32 + s];
        }
        for (int idx = tid; idx < 4096; idx += TPB) {
            const int h = idx >> 5;
            const int s = idx & 31;
            s_wo1[h * 36 + s] = W_o1[h * 768 + i * 32 + s];
        }
        __syncthreads();

        // --- taps; also write appended queue element (cur entering block i) -
        const int d = 1 << (i & 7);
        const size_t rowbase = ((size_t)(i * BATCH + b) * CH + lane);
        const float t0 = queues[rowbase * TQ + (TQ - d)];
        nq[rowbase * TQO + TQ] = cur;
        s_tap[w][lane] = t0;
        s_cur[w][lane] = cur;
        __syncwarp();

        // --- z = tap0 @ Wc0^T + cur @ Wc1^T + b ; lane computes o=lane, lane+32
        float z0 = b_conv[i * 64 + lane];
        float z1 = b_conv[i * 64 + 32 + lane];
#pragma unroll
        for (int c = 0; c < 32; c += 4) {
            const float4 a  = *(const float4*)&s_tap[w][c];
            const float4 u  = *(const float4*)&s_cur[w][c];
            const float4 w00 = *(const float4*)&s_wc0[lane * 36 + c];
            const float4 w10 = *(const float4*)&s_wc1[lane * 36 + c];
            const float4 w01 = *(const float4*)&s_wc0[(lane + 32) * 36 + c];
            const float4 w11 = *(const float4*)&s_wc1[(lane + 32) * 36 + c];
            z0 += a.x * w00.x + a.y * w00.y + a.z * w00.z + a.w * w00.w;
            z0 += u.x * w10.x + u.y * w10.y + u.z * w10.z + u.w * w10.w;
            z1 += a.x * w01.x + a.y * w01.y + a.z * w01.z + a.w * w01.w;
            z1 += u.x * w11.x + u.y * w11.y + u.z * w11.z + u.w * w11.w;
        }

        const float gated = tanhf(z0) * (1.f / (1.f + __expf(-z1)));
        s_g[w][lane] = gated;
        __syncwarp();

        // --- skip / res projections ----------------------------------------
        float sk = b_skip[i * 32 + lane];
        float rs = b_res [i * 32 + lane];
#pragma unroll
        for (int s = 0; s < 32; s += 4) {
            const float4 g  = *(const float4*)&s_g[w][s];
            const float4 wr = *(const float4*)&s_wrs[lane * 36 + s];
            const float4 ws = *(const float4*)&s_wsk[lane * 36 + s];
            rs += g.x * wr.x + g.y * wr.y + g.z * wr.z + g.w * wr.w;
            sk += g.x * ws.x + g.y * ws.y + g.z * ws.z + g.w * ws.w;
        }
        cur = rs + cur;  // + tap1 (= old cur for this channel)

        // relu(skip) staged for the folded W_o1 accumulation
        s_tap[w][lane] = fmaxf(sk, 0.f);
        __syncwarp();

        // --- fold skip head: acc_h += relu(skip_s) * W_o1[h, i*32+s] --------
#pragma unroll
        for (int s = 0; s < 32; s += 4) {
            const float4 sr = *(const float4*)&s_tap[w][s];
            const float4 v0 = *(const float4*)&s_wo1[(lane      ) * 36 + s];
            const float4 v1 = *(const float4*)&s_wo1[(lane + 32 ) * 36 + s];
            const float4 v2 = *(const float4*)&s_wo1[(lane + 64 ) * 36 + s];
            const float4 v3 = *(const float4*)&s_wo1[(lane + 96 ) * 36 + s];
            acc0 += sr.x * v0.x + sr.y * v0.y + sr.z * v0.z + sr.w * v0.w;
            acc1 += sr.x * v1.x + sr.y * v1.y + sr.z * v1.z + sr.w * v1.w;
            acc2 += sr.x * v2.x + sr.y * v2.y + sr.z * v2.z + sr.w * v2.w;
            acc3 += sr.x * v3.x + sr.y * v3.y + sr.z * v3.z + sr.w * v3.w;
        }
        __syncwarp();
    }

    // --- output head: relu(acc + b_o1) @ W_o2 + b_o2 ------------------------
    float p = 0.f;
    p += fmaxf(acc0 + b_o1[lane      ], 0.f) * W_o2[lane      ];
    p += fmaxf(acc1 + b_o1[lane + 32 ], 0.f) * W_o2[lane + 32 ];
    p += fmaxf(acc2 + b_o1[lane + 64 ], 0.f) * W_o2[lane + 64 ];
    p += fmaxf(acc3 + b_o1[lane + 96 ], 0.f) * W_o2[lane + 96 ];
#pragma unroll
    for (int off = 16; off; off >>= 1)
        p += __shfl_xor_sync(0xffffffffu, p, off);
    if (lane == 0)
        out[b] = p + b_o2[0];
}

extern "C" void kernel_launch(void* const* d_in, const int* in_sizes, int n_in,
                              void* d_out, int out_size) {
    const float* queues = (const float*)d_in[0];
    const float* x      = (const float*)d_in[1];
    const float* num    = (const float*)d_in[2];
    const int*   cat    = (const int*)  d_in[3];
    const float* emb    = (const float*)d_in[4];
    const float* W_in   = (const float*)d_in[5];
    const float* b_in   = (const float*)d_in[6];
    const float* W_conv = (const float*)d_in[7];
    const float* b_conv = (const float*)d_in[8];
    const float* W_res  = (const float*)d_in[9];
    const float* b_res  = (const float*)d_in[10];
    const float* W_skip = (const float*)d_in[11];
    const float* b_skip = (const float*)d_in[12];
    const float* W_o1   = (const float*)d_in[13];
    const float* b_o1   = (const float*)d_in[14];
    const float* W_o2   = (const float*)d_in[15];
    const float* b_o2   = (const float*)d_in[16];
    float* out = (float*)d_out;

    dim3 grid(COMPUTE_CTAS + COPY_CTAS);
    dim3 block(TPB);
    wave_fused_kernel<<<grid, block>>>(
        queues, x, num, cat, emb, W_in, b_in, W_conv, b_conv,
        W_res, b_res, W_skip, b_skip, W_o1, b_o1, W_o2, b_o2, out);
}

// round 3
// speedup vs baseline: 1.2230x; 1.2230x over previous
#include <cuda_runtime.h>

#define NBLK 24
#define BATCH 256
#define CH 32
#define TQ 256
#define TQO 257

#define COMPUTE_CTAS 64
#define COPY_CTAS 1024
#define TPB 128

#define NROWS (NBLK * BATCH * CH)   // 196608 rows of 256 floats

__global__ void __launch_bounds__(TPB) wave_fused_kernel(
    const float* __restrict__ queues,   // (24,256,32,256)
    const float* __restrict__ x,        // (256,1,1)
    const float* __restrict__ num,      // (256,8,1)
    const int*   __restrict__ cat,      // (256,1,1)
    const float* __restrict__ emb,      // (1000,16)
    const float* __restrict__ W_in,     // (32,25)
    const float* __restrict__ b_in,     // (32)
    const float* __restrict__ W_conv,   // (24,64,32,2)
    const float* __restrict__ b_conv,   // (24,64)
    const float* __restrict__ W_res,    // (24,32,32)
    const float* __restrict__ b_res,    // (24,32)
    const float* __restrict__ W_skip,   // (24,32,32)
    const float* __restrict__ b_skip,   // (24,32)
    const float* __restrict__ W_o1,     // (128,768)
    const float* __restrict__ b_o1,     // (128)
    const float* __restrict__ W_o2,     // (1,128)
    const float* __restrict__ b_o2,     // (1)
    float* __restrict__ out)            // [256 out][24*256*32*257 new_queues]
{
    float* __restrict__ nq = out + BATCH;  // new_queues region

    if (blockIdx.x >= COMPUTE_CTAS) {
        // ---------------- COPY ROLE: warp-per-row, fully coalesced ----------
        // Lane l copies floats l, l+32, ..., l+224 of each 256-float row.
        // Every LDG.32 / STG.32 is one contiguous 128B warp access.
        const int lane = threadIdx.x & 31;
        const int gw   = (blockIdx.x - COMPUTE_CTAS) * (TPB / 32) + (threadIdx.x >> 5);
        const int wstride = COPY_CTAS * (TPB / 32);
        for (int row = gw; row < NROWS; row += wstride) {
            const float* __restrict__ src = queues + (size_t)row * TQ + lane;
            float*       __restrict__ dst = nq     + (size_t)row * TQO + lane;
            float v0 = src[0];
            float v1 = src[32];
            float v2 = src[64];
            float v3 = src[96];
            float v4 = src[128];
            float v5 = src[160];
            float v6 = src[192];
            float v7 = src[224];
            dst[0]   = v0;
            dst[32]  = v1;
            dst[64]  = v2;
            dst[96]  = v3;
            dst[128] = v4;
            dst[160] = v5;
            dst[192] = v6;
            dst[224] = v7;
        }
        return;
    }

    // ---------------- COMPUTE ROLE: recurrent chain, 1 warp = 1 batch -------
    __shared__ __align__(16) float s_wc0[64 * 36];   // W_conv[..,0]  [o][c]
    __shared__ __align__(16) float s_wc1[64 * 36];   // W_conv[..,1]  [o][c]
    __shared__ __align__(16) float s_wrs[32 * 36];   // W_res  [o][s]
    __shared__ __align__(16) float s_wsk[32 * 36];   // W_skip [o][s]
    __shared__ __align__(16) float s_wo1[128 * 36];  // W_o1 chunk [h][s]
    __shared__ __align__(16) float s_tap[4][32];
    __shared__ __align__(16) float s_cur[4][32];
    __shared__ __align__(16) float s_g[4][32];

    const int tid  = threadIdx.x;
    const int w    = tid >> 5;
    const int lane = tid & 31;
    const int b    = blockIdx.x * 4 + w;

    // --- input projection: inp = [x(1), num(8), emb(16)], cur = W_in @ inp ---
    if (lane < 25) {
        float v;
        if (lane == 0)      v = x[b];
        else if (lane < 9)  v = num[b * 8 + (lane - 1)];
        else                v = emb[cat[b] * 16 + (lane - 9)];
        s_g[w][lane] = v;
    }
    __syncwarp();
    float cur = b_in[lane];
#pragma unroll
    for (int k = 0; k < 25; k++)
        cur += W_in[lane * 25 + k] * s_g[w][k];
    __syncwarp();

    float acc0 = 0.f, acc1 = 0.f, acc2 = 0.f, acc3 = 0.f;  // W_o1 accumulators

    for (int i = 0; i < NBLK; i++) {
        __syncthreads();  // previous iteration done reading weight buffers

        // --- cooperative weight staging into padded shared -----------------
        for (int idx = tid; idx < 4096; idx += TPB) {
            const int o = idx >> 6;
            const int r = idx & 63;
            const int c = r >> 1;
            const int k = r & 1;
            const float v = W_conv[((i * 64 + o) * 32 + c) * 2 + k];
            (k ? s_wc1 : s_wc0)[o * 36 + c] = v;
        }
        for (int idx = tid; idx < 1024; idx += TPB) {
            const int o = idx >> 5;
            const int s = idx & 31;
            s_wrs[o * 36 + s] = W_res [(i * 32 + o) * 32 + s];
            s_wsk[o * 36 + s] = W_skip[(i * 32 + o) * 32 + s];
        }
        for (int idx = tid; idx < 4096; idx += TPB) {
            const int h = idx >> 5;
            const int s = idx & 31;
            s_wo1[h * 36 + s] = W_o1[h * 768 + i * 32 + s];
        }
        __syncthreads();

        // --- taps; also write appended queue element (cur entering block i) -
        const int d = 1 << (i & 7);
        const size_t rowbase = ((size_t)(i * BATCH + b) * CH + lane);
        const float t0 = queues[rowbase * TQ + (TQ - d)];
        nq[rowbase * TQO + TQ] = cur;
        s_tap[w][lane] = t0;
        s_cur[w][lane] = cur;
        __syncwarp();

        // --- z = tap0 @ Wc0^T + cur @ Wc1^T + b ; lane computes o=lane, lane+32
        float z0 = b_conv[i * 64 + lane];
        float z1 = b_conv[i * 64 + 32 + lane];
#pragma unroll
        for (int c = 0; c < 32; c += 4) {
            const float4 a   = *(const float4*)&s_tap[w][c];
            const float4 u   = *(const float4*)&s_cur[w][c];
            const float4 w00 = *(const float4*)&s_wc0[lane * 36 + c];
            const float4 w10 = *(const float4*)&s_wc1[lane * 36 + c];
            const float4 w01 = *(const float4*)&s_wc0[(lane + 32) * 36 + c];
            const float4 w11 = *(const float4*)&s_wc1[(lane + 32) * 36 + c];
            z0 += a.x * w00.x + a.y * w00.y + a.z * w00.z + a.w * w00.w;
            z0 += u.x * w10.x + u.y * w10.y + u.z * w10.z + u.w * w10.w;
            z1 += a.x * w01.x + a.y * w01.y + a.z * w01.z + a.w * w01.w;
            z1 += u.x * w11.x + u.y * w11.y + u.z * w11.z + u.w * w11.w;
        }

        const float gated = tanhf(z0) * (1.f / (1.f + __expf(-z1)));
        s_g[w][lane] = gated;
        __syncwarp();

        // --- skip / res projections ----------------------------------------
        float sk = b_skip[i * 32 + lane];
        float rs = b_res [i * 32 + lane];
#pragma unroll
        for (int s = 0; s < 32; s += 4) {
            const float4 g  = *(const float4*)&s_g[w][s];
            const float4 wr = *(const float4*)&s_wrs[lane * 36 + s];
            const float4 ws = *(const float4*)&s_wsk[lane * 36 + s];
            rs += g.x * wr.x + g.y * wr.y + g.z * wr.z + g.w * wr.w;
            sk += g.x * ws.x + g.y * ws.y + g.z * ws.z + g.w * ws.w;
        }
        cur = rs + cur;  // + tap1 (= old cur for this channel)

        // relu(skip) staged for the folded W_o1 accumulation
        s_tap[w][lane] = fmaxf(sk, 0.f);
        __syncwarp();

        // --- fold skip head: acc_h += relu(skip_s) * W_o1[h, i*32+s] --------
#pragma unroll
        for (int s = 0; s < 32; s += 4) {
            const float4 sr = *(const float4*)&s_tap[w][s];
            const float4 v0 = *(const float4*)&s_wo1[(lane      ) * 36 + s];
            const float4 v1 = *(const float4*)&s_wo1[(lane + 32 ) * 36 + s];
            const float4 v2 = *(const float4*)&s_wo1[(lane + 64 ) * 36 + s];
            const float4 v3 = *(const float4*)&s_wo1[(lane + 96 ) * 36 + s];
            acc0 += sr.x * v0.x + sr.y * v0.y + sr.z * v0.z + sr.w * v0.w;
            acc1 += sr.x * v1.x + sr.y * v1.y + sr.z * v1.z + sr.w * v1.w;
            acc2 += sr.x * v2.x + sr.y * v2.y + sr.z * v2.z + sr.w * v2.w;
            acc3 += sr.x * v3.x + sr.y * v3.y + sr.z * v3.z + sr.w * v3.w;
        }
        __syncwarp();
    }

    // --- output head: relu(acc + b_o1) @ W_o2 + b_o2 ------------------------
    float p = 0.f;
    p += fmaxf(acc0 + b_o1[lane      ], 0.f) * W_o2[lane      ];
    p += fmaxf(acc1 + b_o1[lane + 32 ], 0.f) * W_o2[lane + 32 ];
    p += fmaxf(acc2 + b_o1[lane + 64 ], 0.f) * W_o2[lane + 64 ];
    p += fmaxf(acc3 + b_o1[lane + 96 ], 0.f) * W_o2[lane + 96 ];
#pragma unroll
    for (int off = 16; off; off >>= 1)
        p += __shfl_xor_sync(0xffffffffu, p, off);
    if (lane == 0)
        out[b] = p + b_o2[0];
}

extern "C" void kernel_launch(void* const* d_in, const int* in_sizes, int n_in,
                              void* d_out, int out_size) {
    const float* queues = (const float*)d_in[0];
    const float* x      = (const float*)d_in[1];
    const float* num    = (const float*)d_in[2];
    const int*   cat    = (const int*)  d_in[3];
    const float* emb    = (const float*)d_in[4];
    const float* W_in   = (const float*)d_in[5];
    const float* b_in   = (const float*)d_in[6];
    const float* W_conv = (const float*)d_in[7];
    const float* b_conv = (const float*)d_in[8];
    const float* W_res  = (const float*)d_in[9];
    const float* b_res  = (const float*)d_in[10];
    const float* W_skip = (const float*)d_in[11];
    const float* b_skip = (const float*)d_in[12];
    const float* W_o1   = (const float*)d_in[13];
    const float* b_o1   = (const float*)d_in[14];
    const float* W_o2   = (const float*)d_in[15];
    const float* b_o2   = (const float*)d_in[16];
    float* out = (float*)d_out;

    dim3 grid(COMPUTE_CTAS + COPY_CTAS);
    dim3 block(TPB);
    wave_fused_kernel<<<grid, block>>>(
        queues, x, num, cat, emb, W_in, b_in, W_conv, b_conv,
        W_res, b_res, W_skip, b_skip, W_o1, b_o1, W_o2, b_o2, out);
}